// round 11
// baseline (speedup 1.0000x reference)
#include <cuda_runtime.h>

// PairedKidneyCriticModel: sparse GAT critic, N=4096, H=64, L=3, avg-deg ~33.
// R10 = R7 (58.0us champion) with critical-path scheduling changes only:
//  - k_mask forked onto a side stream, concurrent with gemm0 (event join)
//  - k_prep deleted; attn0 blocks build their own 4 nodes' neighbor lists
//    from g_bits BEFORE PDL_WAIT (overlaps gemm0 tail)
//  - attention math byte-identical to R7.

#define NN 4096
#define HH 64
#define LL 3
#define NW (NN/32)          // 128 mask words per node
#define MAXD 128            // degree cap (mean 33, observed max ~65)
#define SLOPE 0.2f
#define EPSV 1e-5f

#define PDL_WAIT() asm volatile("griddepcontrol.wait;" ::: "memory")
#define PDL_TRIG() asm volatile("griddepcontrol.launch_dependents;" ::: "memory")

// ---- scratch (device globals; no allocation allowed) ----
__device__ unsigned g_bits[NN * NW];        // 2 MB transposed adjacency bits
__device__ unsigned short g_nbr[NN * MAXD]; // 1 MB neighbor ids (ascending)
__device__ int g_deg[NN];
__device__ float g_x [NN * HH];             // embedding (residual input)
__device__ float g_h [NN * HH];             // hidden state
__device__ float g_hw[NN * HH];             // h @ W (L2-resident, 1 MB)
__device__ float g_src[NN];
__device__ float g_dst[NN];
__device__ float g_part[1024];
__device__ int g_cnt;

__device__ __forceinline__ float leaky(float e) { return e >= 0.f ? e : SLOPE * e; }

// ---- 1. mask build: thread per (column i, 128-row chunk); words written once ----
__global__ __launch_bounds__(256) void k_mask(const float* __restrict__ adj) {
    int ib = blockIdx.x & 15;          // 16 i-blocks of 256 columns
    int jc = blockIdx.x >> 4;          // 32 j-chunks of 128 rows
    int i  = ib * 256 + threadIdx.x;
    const float* __restrict__ col = adj + i;
    size_t jbase = (size_t)jc * 128;
    unsigned w0 = 0, w1 = 0, w2 = 0, w3 = 0;
    #pragma unroll 8
    for (int t = 0; t < 32; t++) {
        if (col[(jbase + t) * NN] != 0.f && i != (int)(jbase + t))            w0 |= 1u << t;
        if (col[(jbase + 32 + t) * NN] != 0.f && i != (int)(jbase + 32 + t))  w1 |= 1u << t;
        if (col[(jbase + 64 + t) * NN] != 0.f && i != (int)(jbase + 64 + t))  w2 |= 1u << t;
        if (col[(jbase + 96 + t) * NN] != 0.f && i != (int)(jbase + 96 + t))  w3 |= 1u << t;
    }
    unsigned* __restrict__ dst = &g_bits[i * NW + jc * 4];
    dst[0] = w0; dst[1] = w1; dst[2] = w2; dst[3] = w3;
}

// ---- 2. gemm (+ fused AB/embed when l==0): hw = in @ W[l]; src/dst scores ----
__global__ __launch_bounds__(256) void k_gemm(
        const float* __restrict__ gw, const float* __restrict__ gas,
        const float* __restrict__ gad, int l,
        const float* __restrict__ w1, const float* __restrict__ b1,
        const float* __restrict__ w2, const float* __restrict__ b2,
        const int* __restrict__ tsp, const float* __restrict__ arr,
        const float* __restrict__ dep, const float* __restrict__ hard) {
    __shared__ float Ws[HH * HH];     // 16 KB
    __shared__ float hs[16 * HH];     // 4 KB
    __shared__ float sAB[192];
    const float* __restrict__ W  = gw + l * HH * HH;
    const float* __restrict__ as = gas + l * HH;
    const float* __restrict__ ad = gad + l * HH;
    int tid = threadIdx.x;            // 256
    int rbase = blockIdx.x * 16;      // 256 blocks
    int r  = tid >> 4;
    int c4 = (tid & 15) * 4;
    int row = rbase + r;

    // weight tile load reads only harness inputs — safe pre-wait preamble
    #pragma unroll
    for (int t = 0; t < 16; t++) Ws[t * 256 + tid] = W[t * 256 + tid];

    if (l == 0) {
        if (blockIdx.x == 0 && tid == 0) g_cnt = 0;    // replay-safe reset
        if (tid < 192) {              // collapsed embedding A,B
            int which = tid >> 6, c = tid & 63;
            float acc = 0.f;
            for (int h = 0; h < HH; h++) {
                float w = w2[h * HH + c];
                float cf = (which == 0) ? w1[h] : (which == 1 ? w1[HH + h] : b1[h]);
                acc += cf * w;
            }
            if (which == 2) acc += b2[c];
            sAB[tid] = acc;
        }
        __syncthreads();
        int raw = tsp[0];
        float ts = (raw > -1000000 && raw < 1000000) ? (float)raw : __int_as_float(raw);
        float p = (ts - arr[row]) / (dep[row] - arr[row]);
        float hd = hard[row];
        float4 xv;
        xv.x = p * sAB[c4]     + hd * sAB[HH + c4]     + sAB[2 * HH + c4];
        xv.y = p * sAB[c4 + 1] + hd * sAB[HH + c4 + 1] + sAB[2 * HH + c4 + 1];
        xv.z = p * sAB[c4 + 2] + hd * sAB[HH + c4 + 2] + sAB[2 * HH + c4 + 2];
        xv.w = p * sAB[c4 + 3] + hd * sAB[HH + c4 + 3] + sAB[2 * HH + c4 + 3];
        *(float4*)&hs[r * HH + c4] = xv;
        *(float4*)&g_x[row * HH + c4] = xv;
        __syncthreads();
    } else {
        PDL_WAIT();                   // g_h from previous attention
        #pragma unroll
        for (int t = 0; t < 4; t++) hs[t * 256 + tid] = g_h[rbase * HH + t * 256 + tid];
        __syncthreads();
    }

    float4 acc = make_float4(0.f, 0.f, 0.f, 0.f);
    #pragma unroll
    for (int k = 0; k < HH; k++) {
        float hv = hs[r * HH + k];
        float4 wv = *(const float4*)&Ws[k * HH + c4];
        acc.x += hv * wv.x; acc.y += hv * wv.y;
        acc.z += hv * wv.z; acc.w += hv * wv.w;
    }
    *(float4*)&g_hw[row * HH + c4] = acc;

    float ps = acc.x * as[c4] + acc.y * as[c4 + 1] + acc.z * as[c4 + 2] + acc.w * as[c4 + 3];
    float pd = acc.x * ad[c4] + acc.y * ad[c4 + 1] + acc.z * ad[c4 + 2] + acc.w * ad[c4 + 3];
    #pragma unroll
    for (int off = 8; off; off >>= 1) {
        ps += __shfl_down_sync(0xffffffffu, ps, off, 16);
        pd += __shfl_down_sync(0xffffffffu, pd, off, 16);
    }
    if ((tid & 15) == 0) { g_src[row] = ps; g_dst[row] = pd; }
    PDL_TRIG();
}

// shared attention body (2 warps/node) — identical to R7 ----
__device__ __forceinline__ float4 attn_body(int i, int n, int sub, int lane,
                                            const float* __restrict__ b,
                                            float2 (*spj)[MAXD], float2* s_sw,
                                            float4 (*s_accbuf)[16], bool* holds) {
    int deg = g_deg[i];
    if (sub == 0) {
        float di = g_dst[i];
        float e0 = leaky(g_src[i] + di);            // self-loop score
        ushort4 nv = ((const ushort4*)&g_nbr[i * MAXD])[lane];
        int k0 = lane * 4;
        int jj[4] = {nv.x, nv.y, nv.z, nv.w};
        float e[4];
        float m = e0;
        #pragma unroll
        for (int t = 0; t < 4; t++) {
            e[t] = -1e30f;
            if (k0 + t < deg) e[t] = leaky(g_src[jj[t]] + di);
            m = fmaxf(m, e[t]);
        }
        #pragma unroll
        for (int off = 16; off; off >>= 1)
            m = fmaxf(m, __shfl_xor_sync(0xffffffffu, m, off));
        float w0 = __expf(e0 - m);
        float s = 0.f;
        #pragma unroll
        for (int t = 0; t < 4; t++) {
            if (k0 + t < deg) {
                float p = __expf(e[t] - m);
                s += p;
                spj[n][k0 + t] = make_float2(p, __int_as_float(jj[t] * HH));
            }
        }
        #pragma unroll
        for (int off = 16; off; off >>= 1) s += __shfl_xor_sync(0xffffffffu, s, off);
        s += w0;
        if (lane == 0) s_sw[n] = make_float2(w0, 1.0f / s);
    }
    __syncthreads();

    int half = lane >> 4;
    int q    = sub * 2 + half;
    int f4   = (lane & 15) << 2;
    float2 ws = s_sw[n];
    float4 acc = make_float4(0.f, 0.f, 0.f, 0.f);
    if (q == 0) {
        float4 hv = *(const float4*)&g_hw[i * HH + f4];
        acc.x = ws.x * hv.x; acc.y = ws.x * hv.y;
        acc.z = ws.x * hv.z; acc.w = ws.x * hv.w;
    }
    #pragma unroll 4
    for (int k = q; k < deg; k += 4) {
        float2 pj = spj[n][k];
        const float4 hv = *(const float4*)&g_hw[__float_as_int(pj.y) + f4];
        acc.x += pj.x * hv.x; acc.y += pj.x * hv.y;
        acc.z += pj.x * hv.z; acc.w += pj.x * hv.w;
    }
    acc.x += __shfl_xor_sync(0xffffffffu, acc.x, 16);
    acc.y += __shfl_xor_sync(0xffffffffu, acc.y, 16);
    acc.z += __shfl_xor_sync(0xffffffffu, acc.z, 16);
    acc.w += __shfl_xor_sync(0xffffffffu, acc.w, 16);
    if (sub == 1 && half == 0) s_accbuf[n][lane] = acc;
    __syncthreads();
    *holds = (sub == 0 && half == 0);
    float4 o = make_float4(0.f, 0.f, 0.f, 0.f);
    if (*holds) {
        float4 o2 = s_accbuf[n][lane];
        float inv = ws.y;
        o.x = (acc.x + o2.x) * inv + b[f4];
        o.y = (acc.y + o2.y) * inv + b[f4 + 1];
        o.z = (acc.z + o2.z) * inv + b[f4 + 2];
        o.w = (acc.w + o2.w) * inv + b[f4 + 3];
    }
    return o;
}

// builds neighbor list for node i (one warp); identical scan to old k_prep
__device__ __forceinline__ void build_nbr(int i, int lane) {
    const unsigned* __restrict__ bm = &g_bits[i * NW];
    unsigned short* __restrict__ nb = &g_nbr[i * MAXD];
    int base = 0;
    #pragma unroll
    for (int r = 0; r < 4; r++) {
        unsigned word = bm[r * 32 + lane];
        int cnt = __popc(word);
        int pre = cnt;
        #pragma unroll
        for (int off = 1; off < 32; off <<= 1) {
            int v = __shfl_up_sync(0xffffffffu, pre, off);
            if (lane >= off) pre += v;
        }
        int total = __shfl_sync(0xffffffffu, pre, 31);
        int o = base + pre - cnt;
        while (word) {
            int b = __ffs(word) - 1; word &= word - 1;
            if (o < MAXD) nb[o] = (unsigned short)(r * 1024 + lane * 32 + b);
            o++;
        }
        base += total;
    }
    if (lane == 0) g_deg[i] = (base < MAXD) ? base : MAXD;
}

// ---- 3. attention layers 0,1: relu + store g_h. l==0 builds nbr lists. ----
__global__ __launch_bounds__(256) void k_attn(const float* __restrict__ gb, int l) {
    __shared__ float2 spj[4][MAXD];
    __shared__ float2 s_sw[4];
    __shared__ float4 s_accbuf[4][16];
    int warp = threadIdx.x >> 5, lane = threadIdx.x & 31;
    int n = warp >> 1, sub = warp & 1;
    int i = blockIdx.x * 4 + n;           // 1024 blocks
    if (l == 0) {
        // g_bits ready via full event dependency on k_mask; runs BEFORE
        // PDL_WAIT so it overlaps gemm0's tail.
        if (sub == 0) build_nbr(i, lane);
        __syncthreads();
    }
    PDL_WAIT();                           // gemm outputs (src/dst/hw)
    bool holds;
    float4 o = attn_body(i, n, sub, lane, gb + l * HH, spj, s_sw, s_accbuf, &holds);
    if (holds) {
        o.x = fmaxf(o.x, 0.f); o.y = fmaxf(o.y, 0.f);
        o.z = fmaxf(o.z, 0.f); o.w = fmaxf(o.w, 0.f);
        *(float4*)&g_h[i * HH + ((lane & 15) << 2)] = o;
    }
    PDL_TRIG();
}

// ---- 4. attention layer 2 fused with residual+layernorm+value+global reduce ----
__global__ __launch_bounds__(256) void k_attn2(const float* __restrict__ gb,
                                               const float* __restrict__ vw,
                                               const float* __restrict__ vb,
                                               float* __restrict__ out) {
    __shared__ float2 spj[4][MAXD];
    __shared__ float2 s_sw[4];
    __shared__ float4 s_accbuf[4][16];
    __shared__ float s_node[4];
    __shared__ int islast;
    __shared__ float s_red[256];
    PDL_WAIT();
    int warp = threadIdx.x >> 5, lane = threadIdx.x & 31;
    int n = warp >> 1, sub = warp & 1;
    int i = blockIdx.x * 4 + n;           // 1024 blocks
    bool holds;
    float4 o = attn_body(i, n, sub, lane, gb + 2 * HH, spj, s_sw, s_accbuf, &holds);

    if (holds) {                          // 16 lanes of warp sub==0 per node
        int f4 = (lane & 15) << 2;
        float4 xv = *(const float4*)&g_x[i * HH + f4];
        float v0 = xv.x + o.x, v1 = xv.y + o.y, v2 = xv.z + o.z, v3 = xv.w + o.w;
        float sm = v0 + v1 + v2 + v3;
        #pragma unroll
        for (int off = 8; off; off >>= 1) sm += __shfl_xor_sync(0x0000ffffu, sm, off, 16);
        float mu = sm * (1.0f / 64.0f);
        float d0 = v0 - mu, d1 = v1 - mu, d2 = v2 - mu, d3 = v3 - mu;
        float vs = d0 * d0 + d1 * d1 + d2 * d2 + d3 * d3;
        #pragma unroll
        for (int off = 8; off; off >>= 1) vs += __shfl_xor_sync(0x0000ffffu, vs, off, 16);
        float rstd = rsqrtf(vs * (1.0f / 64.0f) + EPSV);
        float yr = (d0 * vw[f4] + d1 * vw[f4 + 1] + d2 * vw[f4 + 2] + d3 * vw[f4 + 3]) * rstd;
        #pragma unroll
        for (int off = 8; off; off >>= 1) yr += __shfl_xor_sync(0x0000ffffu, yr, off, 16);
        if (lane == 0) s_node[n] = yr;
    }
    __syncthreads();
    if (threadIdx.x == 0) {
        float t = s_node[0] + s_node[1] + s_node[2] + s_node[3];   // fixed order
        g_part[blockIdx.x] = t;
        __threadfence();
        islast = (atomicAdd(&g_cnt, 1) == 1023);
    }
    __syncthreads();
    if (islast) {
        __threadfence();
        int tid = threadIdx.x;
        float v = 0.f;
        #pragma unroll
        for (int k = 0; k < 4; k++) v += g_part[tid + k * 256];    // fixed order
        s_red[tid] = v;
        __syncthreads();
        #pragma unroll
        for (int off = 128; off; off >>= 1) {
            if (tid < off) s_red[tid] += s_red[tid + off];
            __syncthreads();
        }
        if (tid == 0)
            out[0] = fmaxf(0.0f, s_red[0] * (1.0f / NN) + vb[0]);
    }
}

static void launch_pdl(void* func, dim3 grid, dim3 block, void** args) {
    cudaLaunchConfig_t cfg = {};
    cfg.gridDim = grid;
    cfg.blockDim = block;
    cfg.stream = 0;
    cudaLaunchAttribute attr[1];
    attr[0].id = cudaLaunchAttributeProgrammaticStreamSerialization;
    attr[0].val.programmaticStreamSerializationAllowed = 1;
    cfg.attrs = attr;
    cfg.numAttrs = 1;
    cudaLaunchKernelExC(&cfg, func, args);
}

extern "C" void kernel_launch(void* const* d_in, const int* in_sizes, int n_in,
                              void* d_out, int out_size) {
    const float* adj  = (const float*)d_in[0];
    const int*   ts   = (const int*)  d_in[1];
    const float* arr  = (const float*)d_in[2];
    const float* dep  = (const float*)d_in[3];
    const float* hard = (const float*)d_in[4];
    const float* w1 = (const float*)d_in[6];
    const float* b1 = (const float*)d_in[7];
    const float* w2 = (const float*)d_in[8];
    const float* b2 = (const float*)d_in[9];
    const float* gw  = (const float*)d_in[10];
    const float* gas = (const float*)d_in[11];
    const float* gad = (const float*)d_in[12];
    const float* gb  = (const float*)d_in[13];
    const float* vw  = (const float*)d_in[14];
    const float* vb  = (const float*)d_in[15];
    float* out = (float*)d_out;

    // side stream + fork/join events (created once; creation happens on the
    // uncaptured correctness call, reused during capture)
    static cudaStream_t s1 = nullptr;
    static cudaEvent_t e0 = nullptr, e1 = nullptr;
    if (!s1) {
        cudaStreamCreateWithFlags(&s1, cudaStreamNonBlocking);
        cudaEventCreateWithFlags(&e0, cudaEventDisableTiming);
        cudaEventCreateWithFlags(&e1, cudaEventDisableTiming);
    }

    // fork: mask on s1, concurrent with gemm0 on stream 0
    cudaEventRecord(e0, 0);
    cudaStreamWaitEvent(s1, e0, 0);
    k_mask<<<512, 256, 0, s1>>>(adj);
    cudaEventRecord(e1, s1);

    for (int l = 0; l < LL; l++) {
        void* ga[] = {(void*)&gw, (void*)&gas, (void*)&gad, (void*)&l,
                      (void*)&w1, (void*)&b1, (void*)&w2, (void*)&b2,
                      (void*)&ts, (void*)&arr, (void*)&dep, (void*)&hard};
        launch_pdl((void*)k_gemm, dim3(256), dim3(256), ga);
        if (l == 0) cudaStreamWaitEvent(0, e1, 0);   // join: attn0 needs g_bits
        if (l < LL - 1) {
            void* aa[] = {(void*)&gb, (void*)&l};
            launch_pdl((void*)k_attn, dim3(1024), dim3(256), aa);
        } else {
            void* aa[] = {(void*)&gb, (void*)&vw, (void*)&vb, (void*)&out};
            launch_pdl((void*)k_attn2, dim3(1024), dim3(256), aa);
        }
    }
}

// round 12
// speedup vs baseline: 1.3288x; 1.3288x over previous
#include <cuda_runtime.h>

// PairedKidneyCriticModel: sparse GAT critic, N=4096, H=64, L=3, avg-deg ~33.
// R11 = R7 (58.0us champion) with in-kernel heterogeneous fusion:
//  - ONE kernel runs gemm0+embed (blocks 0..255) AND the adjacency scan
//    (blocks 256..767) — independent roles, gemm0 hides under the DRAM scan.
//  - k_prep deleted: attn0 builds its nodes' neighbor lists post-PDL_WAIT.
//  - 6 launches total, single-stream PDL chain. Attention math = R7.

#define NN 4096
#define HH 64
#define LL 3
#define NW (NN/32)          // 128 mask words per node
#define MAXD 128            // degree cap (mean 33, observed max ~65)
#define SLOPE 0.2f
#define EPSV 1e-5f

#define PDL_WAIT() asm volatile("griddepcontrol.wait;" ::: "memory")
#define PDL_TRIG() asm volatile("griddepcontrol.launch_dependents;" ::: "memory")

// ---- scratch (device globals; no allocation allowed) ----
__device__ unsigned g_bits[NN * NW];        // 2 MB transposed adjacency bits
__device__ unsigned short g_nbr[NN * MAXD]; // 1 MB neighbor ids (ascending)
__device__ int g_deg[NN];
__device__ float g_x [NN * HH];             // embedding (residual input)
__device__ float g_h [NN * HH];             // hidden state
__device__ float g_hw[NN * HH];             // h @ W (L2-resident, 1 MB)
__device__ float g_src[NN];
__device__ float g_dst[NN];
__device__ float g_part[1024];
__device__ int g_cnt;

__device__ __forceinline__ float leaky(float e) { return e >= 0.f ? e : SLOPE * e; }

// ---- 1. fused first kernel: gemm0+embed (blocks<256) | mask scan (blocks>=256) ----
__global__ __launch_bounds__(256) void k_fuse0(
        const float* __restrict__ adj,
        const float* __restrict__ gw, const float* __restrict__ gas,
        const float* __restrict__ gad,
        const float* __restrict__ w1, const float* __restrict__ b1,
        const float* __restrict__ w2, const float* __restrict__ b2,
        const int* __restrict__ tsp, const float* __restrict__ arr,
        const float* __restrict__ dep, const float* __restrict__ hard) {
    __shared__ float Ws[HH * HH];     // 16 KB (gemm role only)
    __shared__ float hs[16 * HH];     // 4 KB
    __shared__ float sAB[192];
    int tid = threadIdx.x;            // 256

    if (blockIdx.x >= 256) {
        // ------- mask role: thread per (column i, 128-row chunk) -------
        int mb = blockIdx.x - 256;    // 0..511
        int ib = mb & 15;             // 16 i-blocks of 256 columns
        int jc = mb >> 4;             // 32 j-chunks of 128 rows
        int i  = ib * 256 + tid;
        const float* __restrict__ col = adj + i;
        size_t jbase = (size_t)jc * 128;
        unsigned m0 = 0, m1 = 0, m2 = 0, m3 = 0;
        #pragma unroll 8
        for (int t = 0; t < 32; t++) {
            if (col[(jbase + t) * NN] != 0.f && i != (int)(jbase + t))            m0 |= 1u << t;
            if (col[(jbase + 32 + t) * NN] != 0.f && i != (int)(jbase + 32 + t))  m1 |= 1u << t;
            if (col[(jbase + 64 + t) * NN] != 0.f && i != (int)(jbase + 64 + t))  m2 |= 1u << t;
            if (col[(jbase + 96 + t) * NN] != 0.f && i != (int)(jbase + 96 + t))  m3 |= 1u << t;
        }
        unsigned* __restrict__ dst = &g_bits[i * NW + jc * 4];
        dst[0] = m0; dst[1] = m1; dst[2] = m2; dst[3] = m3;
    } else {
        // ------- gemm0 + embed role (identical math to R7 l==0 path) -------
        const float* __restrict__ W  = gw;          // layer 0
        const float* __restrict__ as = gas;
        const float* __restrict__ ad = gad;
        int rbase = blockIdx.x * 16;
        int r  = tid >> 4;
        int c4 = (tid & 15) * 4;
        int row = rbase + r;

        if (blockIdx.x == 0 && tid == 0) g_cnt = 0;   // replay-safe reset
        #pragma unroll
        for (int t = 0; t < 16; t++) Ws[t * 256 + tid] = W[t * 256 + tid];
        if (tid < 192) {              // collapsed embedding A,B
            int which = tid >> 6, c = tid & 63;
            float acc = 0.f;
            for (int h = 0; h < HH; h++) {
                float w = w2[h * HH + c];
                float cf = (which == 0) ? w1[h] : (which == 1 ? w1[HH + h] : b1[h]);
                acc += cf * w;
            }
            if (which == 2) acc += b2[c];
            sAB[tid] = acc;
        }
        __syncthreads();
        int raw = tsp[0];
        float ts = (raw > -1000000 && raw < 1000000) ? (float)raw : __int_as_float(raw);
        float p = (ts - arr[row]) / (dep[row] - arr[row]);
        float hd = hard[row];
        float4 xv;
        xv.x = p * sAB[c4]     + hd * sAB[HH + c4]     + sAB[2 * HH + c4];
        xv.y = p * sAB[c4 + 1] + hd * sAB[HH + c4 + 1] + sAB[2 * HH + c4 + 1];
        xv.z = p * sAB[c4 + 2] + hd * sAB[HH + c4 + 2] + sAB[2 * HH + c4 + 2];
        xv.w = p * sAB[c4 + 3] + hd * sAB[HH + c4 + 3] + sAB[2 * HH + c4 + 3];
        *(float4*)&hs[r * HH + c4] = xv;
        *(float4*)&g_x[row * HH + c4] = xv;
        __syncthreads();

        float4 acc = make_float4(0.f, 0.f, 0.f, 0.f);
        #pragma unroll
        for (int k = 0; k < HH; k++) {
            float hv = hs[r * HH + k];
            float4 wv = *(const float4*)&Ws[k * HH + c4];
            acc.x += hv * wv.x; acc.y += hv * wv.y;
            acc.z += hv * wv.z; acc.w += hv * wv.w;
        }
        *(float4*)&g_hw[row * HH + c4] = acc;

        float ps = acc.x * as[c4] + acc.y * as[c4 + 1] + acc.z * as[c4 + 2] + acc.w * as[c4 + 3];
        float pd = acc.x * ad[c4] + acc.y * ad[c4 + 1] + acc.z * ad[c4 + 2] + acc.w * ad[c4 + 3];
        #pragma unroll
        for (int off = 8; off; off >>= 1) {
            ps += __shfl_down_sync(0xffffffffu, ps, off, 16);
            pd += __shfl_down_sync(0xffffffffu, pd, off, 16);
        }
        if ((tid & 15) == 0) { g_src[row] = ps; g_dst[row] = pd; }
    }
    PDL_TRIG();
}

// ---- 2. gemm layers 1,2: hw = g_h @ W[l]; src/dst scores ----
__global__ __launch_bounds__(256) void k_gemm(
        const float* __restrict__ gw, const float* __restrict__ gas,
        const float* __restrict__ gad, int l) {
    __shared__ float Ws[HH * HH];     // 16 KB
    __shared__ float hs[16 * HH];     // 4 KB
    const float* __restrict__ W  = gw + l * HH * HH;
    const float* __restrict__ as = gas + l * HH;
    const float* __restrict__ ad = gad + l * HH;
    int tid = threadIdx.x;            // 256
    int rbase = blockIdx.x * 16;      // 256 blocks
    int r  = tid >> 4;
    int c4 = (tid & 15) * 4;
    int row = rbase + r;

    // weight tile load reads only harness inputs — safe pre-wait preamble
    #pragma unroll
    for (int t = 0; t < 16; t++) Ws[t * 256 + tid] = W[t * 256 + tid];

    PDL_WAIT();                       // g_h from previous attention
    #pragma unroll
    for (int t = 0; t < 4; t++) hs[t * 256 + tid] = g_h[rbase * HH + t * 256 + tid];
    __syncthreads();

    float4 acc = make_float4(0.f, 0.f, 0.f, 0.f);
    #pragma unroll
    for (int k = 0; k < HH; k++) {
        float hv = hs[r * HH + k];
        float4 wv = *(const float4*)&Ws[k * HH + c4];
        acc.x += hv * wv.x; acc.y += hv * wv.y;
        acc.z += hv * wv.z; acc.w += hv * wv.w;
    }
    *(float4*)&g_hw[row * HH + c4] = acc;

    float ps = acc.x * as[c4] + acc.y * as[c4 + 1] + acc.z * as[c4 + 2] + acc.w * as[c4 + 3];
    float pd = acc.x * ad[c4] + acc.y * ad[c4 + 1] + acc.z * ad[c4 + 2] + acc.w * ad[c4 + 3];
    #pragma unroll
    for (int off = 8; off; off >>= 1) {
        ps += __shfl_down_sync(0xffffffffu, ps, off, 16);
        pd += __shfl_down_sync(0xffffffffu, pd, off, 16);
    }
    if ((tid & 15) == 0) { g_src[row] = ps; g_dst[row] = pd; }
    PDL_TRIG();
}

// shared attention body (2 warps/node) — identical to R7
__device__ __forceinline__ float4 attn_body(int i, int n, int sub, int lane,
                                            const float* __restrict__ b,
                                            float2 (*spj)[MAXD], float2* s_sw,
                                            float4 (*s_accbuf)[16], bool* holds) {
    int deg = g_deg[i];
    if (sub == 0) {
        float di = g_dst[i];
        float e0 = leaky(g_src[i] + di);            // self-loop score
        ushort4 nv = ((const ushort4*)&g_nbr[i * MAXD])[lane];
        int k0 = lane * 4;
        int jj[4] = {nv.x, nv.y, nv.z, nv.w};
        float e[4];
        float m = e0;
        #pragma unroll
        for (int t = 0; t < 4; t++) {
            e[t] = -1e30f;
            if (k0 + t < deg) e[t] = leaky(g_src[jj[t]] + di);
            m = fmaxf(m, e[t]);
        }
        #pragma unroll
        for (int off = 16; off; off >>= 1)
            m = fmaxf(m, __shfl_xor_sync(0xffffffffu, m, off));
        float w0 = __expf(e0 - m);
        float s = 0.f;
        #pragma unroll
        for (int t = 0; t < 4; t++) {
            if (k0 + t < deg) {
                float p = __expf(e[t] - m);
                s += p;
                spj[n][k0 + t] = make_float2(p, __int_as_float(jj[t] * HH));
            }
        }
        #pragma unroll
        for (int off = 16; off; off >>= 1) s += __shfl_xor_sync(0xffffffffu, s, off);
        s += w0;
        if (lane == 0) s_sw[n] = make_float2(w0, 1.0f / s);
    }
    __syncthreads();

    int half = lane >> 4;
    int q    = sub * 2 + half;
    int f4   = (lane & 15) << 2;
    float2 ws = s_sw[n];
    float4 acc = make_float4(0.f, 0.f, 0.f, 0.f);
    if (q == 0) {
        float4 hv = *(const float4*)&g_hw[i * HH + f4];
        acc.x = ws.x * hv.x; acc.y = ws.x * hv.y;
        acc.z = ws.x * hv.z; acc.w = ws.x * hv.w;
    }
    #pragma unroll 4
    for (int k = q; k < deg; k += 4) {
        float2 pj = spj[n][k];
        const float4 hv = *(const float4*)&g_hw[__float_as_int(pj.y) + f4];
        acc.x += pj.x * hv.x; acc.y += pj.x * hv.y;
        acc.z += pj.x * hv.z; acc.w += pj.x * hv.w;
    }
    acc.x += __shfl_xor_sync(0xffffffffu, acc.x, 16);
    acc.y += __shfl_xor_sync(0xffffffffu, acc.y, 16);
    acc.z += __shfl_xor_sync(0xffffffffu, acc.z, 16);
    acc.w += __shfl_xor_sync(0xffffffffu, acc.w, 16);
    if (sub == 1 && half == 0) s_accbuf[n][lane] = acc;
    __syncthreads();
    *holds = (sub == 0 && half == 0);
    float4 o = make_float4(0.f, 0.f, 0.f, 0.f);
    if (*holds) {
        float4 o2 = s_accbuf[n][lane];
        float inv = ws.y;
        o.x = (acc.x + o2.x) * inv + b[f4];
        o.y = (acc.y + o2.y) * inv + b[f4 + 1];
        o.z = (acc.z + o2.z) * inv + b[f4 + 2];
        o.w = (acc.w + o2.w) * inv + b[f4 + 3];
    }
    return o;
}

// builds neighbor list for node i (one warp); identical scan to old k_prep
__device__ __forceinline__ void build_nbr(int i, int lane) {
    const unsigned* __restrict__ bm = &g_bits[i * NW];
    unsigned short* __restrict__ nb = &g_nbr[i * MAXD];
    int base = 0;
    #pragma unroll
    for (int r = 0; r < 4; r++) {
        unsigned word = bm[r * 32 + lane];
        int cnt = __popc(word);
        int pre = cnt;
        #pragma unroll
        for (int off = 1; off < 32; off <<= 1) {
            int v = __shfl_up_sync(0xffffffffu, pre, off);
            if (lane >= off) pre += v;
        }
        int total = __shfl_sync(0xffffffffu, pre, 31);
        int o = base + pre - cnt;
        while (word) {
            int b = __ffs(word) - 1; word &= word - 1;
            if (o < MAXD) nb[o] = (unsigned short)(r * 1024 + lane * 32 + b);
            o++;
        }
        base += total;
    }
    if (lane == 0) g_deg[i] = (base < MAXD) ? base : MAXD;
}

// ---- 3. attention layers 0,1: relu + store g_h. l==0 builds nbr lists first. ----
__global__ __launch_bounds__(256) void k_attn(const float* __restrict__ gb, int l) {
    __shared__ float2 spj[4][MAXD];
    __shared__ float2 s_sw[4];
    __shared__ float4 s_accbuf[4][16];
    PDL_WAIT();                           // fused kernel (bits+gemm0) or gemm_l
    int warp = threadIdx.x >> 5, lane = threadIdx.x & 31;
    int n = warp >> 1, sub = warp & 1;
    int i = blockIdx.x * 4 + n;           // 1024 blocks
    if (l == 0) {
        if (sub == 0) build_nbr(i, lane);
        __syncthreads();                  // g_deg/g_nbr visible block-wide
    }
    bool holds;
    float4 o = attn_body(i, n, sub, lane, gb + l * HH, spj, s_sw, s_accbuf, &holds);
    if (holds) {
        o.x = fmaxf(o.x, 0.f); o.y = fmaxf(o.y, 0.f);
        o.z = fmaxf(o.z, 0.f); o.w = fmaxf(o.w, 0.f);
        *(float4*)&g_h[i * HH + ((lane & 15) << 2)] = o;
    }
    PDL_TRIG();
}

// ---- 4. attention layer 2 fused with residual+layernorm+value+global reduce ----
__global__ __launch_bounds__(256) void k_attn2(const float* __restrict__ gb,
                                               const float* __restrict__ vw,
                                               const float* __restrict__ vb,
                                               float* __restrict__ out) {
    __shared__ float2 spj[4][MAXD];
    __shared__ float2 s_sw[4];
    __shared__ float4 s_accbuf[4][16];
    __shared__ float s_node[4];
    __shared__ int islast;
    __shared__ float s_red[256];
    PDL_WAIT();
    int warp = threadIdx.x >> 5, lane = threadIdx.x & 31;
    int n = warp >> 1, sub = warp & 1;
    int i = blockIdx.x * 4 + n;           // 1024 blocks
    bool holds;
    float4 o = attn_body(i, n, sub, lane, gb + 2 * HH, spj, s_sw, s_accbuf, &holds);

    if (holds) {                          // 16 lanes of warp sub==0 per node
        int f4 = (lane & 15) << 2;
        float4 xv = *(const float4*)&g_x[i * HH + f4];
        float v0 = xv.x + o.x, v1 = xv.y + o.y, v2 = xv.z + o.z, v3 = xv.w + o.w;
        float sm = v0 + v1 + v2 + v3;
        #pragma unroll
        for (int off = 8; off; off >>= 1) sm += __shfl_xor_sync(0x0000ffffu, sm, off, 16);
        float mu = sm * (1.0f / 64.0f);
        float d0 = v0 - mu, d1 = v1 - mu, d2 = v2 - mu, d3 = v3 - mu;
        float vs = d0 * d0 + d1 * d1 + d2 * d2 + d3 * d3;
        #pragma unroll
        for (int off = 8; off; off >>= 1) vs += __shfl_xor_sync(0x0000ffffu, vs, off, 16);
        float rstd = rsqrtf(vs * (1.0f / 64.0f) + EPSV);
        float yr = (d0 * vw[f4] + d1 * vw[f4 + 1] + d2 * vw[f4 + 2] + d3 * vw[f4 + 3]) * rstd;
        #pragma unroll
        for (int off = 8; off; off >>= 1) yr += __shfl_xor_sync(0x0000ffffu, yr, off, 16);
        if (lane == 0) s_node[n] = yr;
    }
    __syncthreads();
    if (threadIdx.x == 0) {
        float t = s_node[0] + s_node[1] + s_node[2] + s_node[3];   // fixed order
        g_part[blockIdx.x] = t;
        __threadfence();
        islast = (atomicAdd(&g_cnt, 1) == 1023);
    }
    __syncthreads();
    if (islast) {
        __threadfence();
        int tid = threadIdx.x;
        float v = 0.f;
        #pragma unroll
        for (int k = 0; k < 4; k++) v += g_part[tid + k * 256];    // fixed order
        s_red[tid] = v;
        __syncthreads();
        #pragma unroll
        for (int off = 128; off; off >>= 1) {
            if (tid < off) s_red[tid] += s_red[tid + off];
            __syncthreads();
        }
        if (tid == 0)
            out[0] = fmaxf(0.0f, s_red[0] * (1.0f / NN) + vb[0]);
    }
}

static void launch_pdl(void* func, dim3 grid, dim3 block, void** args) {
    cudaLaunchConfig_t cfg = {};
    cfg.gridDim = grid;
    cfg.blockDim = block;
    cfg.stream = 0;
    cudaLaunchAttribute attr[1];
    attr[0].id = cudaLaunchAttributeProgrammaticStreamSerialization;
    attr[0].val.programmaticStreamSerializationAllowed = 1;
    cfg.attrs = attr;
    cfg.numAttrs = 1;
    cudaLaunchKernelExC(&cfg, func, args);
}

extern "C" void kernel_launch(void* const* d_in, const int* in_sizes, int n_in,
                              void* d_out, int out_size) {
    const float* adj  = (const float*)d_in[0];
    const int*   ts   = (const int*)  d_in[1];
    const float* arr  = (const float*)d_in[2];
    const float* dep  = (const float*)d_in[3];
    const float* hard = (const float*)d_in[4];
    const float* w1 = (const float*)d_in[6];
    const float* b1 = (const float*)d_in[7];
    const float* w2 = (const float*)d_in[8];
    const float* b2 = (const float*)d_in[9];
    const float* gw  = (const float*)d_in[10];
    const float* gas = (const float*)d_in[11];
    const float* gad = (const float*)d_in[12];
    const float* gb  = (const float*)d_in[13];
    const float* vw  = (const float*)d_in[14];
    const float* vb  = (const float*)d_in[15];
    float* out = (float*)d_out;

    k_fuse0<<<768, 256>>>(adj, gw, gas, gad, w1, b1, w2, b2, ts, arr, dep, hard);

    {   int l0 = 0;
        void* aa[] = {(void*)&gb, (void*)&l0};
        launch_pdl((void*)k_attn, dim3(1024), dim3(256), aa); }

    for (int l = 1; l < LL; l++) {
        void* ga[] = {(void*)&gw, (void*)&gas, (void*)&gad, (void*)&l};
        launch_pdl((void*)k_gemm, dim3(256), dim3(256), ga);
        if (l < LL - 1) {
            void* aa[] = {(void*)&gb, (void*)&l};
            launch_pdl((void*)k_attn, dim3(1024), dim3(256), aa);
        } else {
            void* aa[] = {(void*)&gb, (void*)&vw, (void*)&vb, (void*)&out};
            launch_pdl((void*)k_attn2, dim3(1024), dim3(256), aa);
        }
    }
}

// round 13
// speedup vs baseline: 1.3786x; 1.0375x over previous
#include <cuda_runtime.h>

// PairedKidneyCriticModel: sparse GAT critic, N=4096, H=64, L=3, avg-deg ~33.
// R12 = R11 (49.6us champion) + two cuts:
//  - softmax pivots on the self-loop score e0 (shift-invariance) => the
//    5-step SHFL max-reduce chain is deleted from every node's critical path
//  - gemm layers 1,2 use 32-row tiles => 128 blocks, single wave

#define NN 4096
#define HH 64
#define LL 3
#define NW (NN/32)          // 128 mask words per node
#define MAXD 128            // degree cap (mean 33, observed max ~65)
#define SLOPE 0.2f
#define EPSV 1e-5f

#define PDL_WAIT() asm volatile("griddepcontrol.wait;" ::: "memory")
#define PDL_TRIG() asm volatile("griddepcontrol.launch_dependents;" ::: "memory")

// ---- scratch (device globals; no allocation allowed) ----
__device__ unsigned g_bits[NN * NW];        // 2 MB transposed adjacency bits
__device__ unsigned short g_nbr[NN * MAXD]; // 1 MB neighbor ids (ascending)
__device__ int g_deg[NN];
__device__ float g_x [NN * HH];             // embedding (residual input)
__device__ float g_h [NN * HH];             // hidden state
__device__ float g_hw[NN * HH];             // h @ W (L2-resident, 1 MB)
__device__ float g_src[NN];
__device__ float g_dst[NN];
__device__ float g_part[1024];
__device__ int g_cnt;

__device__ __forceinline__ float leaky(float e) { return e >= 0.f ? e : SLOPE * e; }

// ---- 1. fused first kernel: gemm0+embed (blocks<256) | mask scan (blocks>=256) ----
__global__ __launch_bounds__(256) void k_fuse0(
        const float* __restrict__ adj,
        const float* __restrict__ gw, const float* __restrict__ gas,
        const float* __restrict__ gad,
        const float* __restrict__ w1, const float* __restrict__ b1,
        const float* __restrict__ w2, const float* __restrict__ b2,
        const int* __restrict__ tsp, const float* __restrict__ arr,
        const float* __restrict__ dep, const float* __restrict__ hard) {
    __shared__ float Ws[HH * HH];     // 16 KB (gemm role only)
    __shared__ float hs[16 * HH];     // 4 KB
    __shared__ float sAB[192];
    int tid = threadIdx.x;            // 256

    if (blockIdx.x >= 256) {
        // ------- mask role: thread per (column i, 128-row chunk) -------
        int mb = blockIdx.x - 256;    // 0..511
        int ib = mb & 15;             // 16 i-blocks of 256 columns
        int jc = mb >> 4;             // 32 j-chunks of 128 rows
        int i  = ib * 256 + tid;
        const float* __restrict__ col = adj + i;
        size_t jbase = (size_t)jc * 128;
        unsigned m0 = 0, m1 = 0, m2 = 0, m3 = 0;
        #pragma unroll 8
        for (int t = 0; t < 32; t++) {
            if (col[(jbase + t) * NN] != 0.f && i != (int)(jbase + t))            m0 |= 1u << t;
            if (col[(jbase + 32 + t) * NN] != 0.f && i != (int)(jbase + 32 + t))  m1 |= 1u << t;
            if (col[(jbase + 64 + t) * NN] != 0.f && i != (int)(jbase + 64 + t))  m2 |= 1u << t;
            if (col[(jbase + 96 + t) * NN] != 0.f && i != (int)(jbase + 96 + t))  m3 |= 1u << t;
        }
        unsigned* __restrict__ dst = &g_bits[i * NW + jc * 4];
        dst[0] = m0; dst[1] = m1; dst[2] = m2; dst[3] = m3;
    } else {
        // ------- gemm0 + embed role -------
        const float* __restrict__ W  = gw;          // layer 0
        const float* __restrict__ as = gas;
        const float* __restrict__ ad = gad;
        int rbase = blockIdx.x * 16;
        int r  = tid >> 4;
        int c4 = (tid & 15) * 4;
        int row = rbase + r;

        if (blockIdx.x == 0 && tid == 0) g_cnt = 0;   // replay-safe reset
        #pragma unroll
        for (int t = 0; t < 16; t++) Ws[t * 256 + tid] = W[t * 256 + tid];
        if (tid < 192) {              // collapsed embedding A,B
            int which = tid >> 6, c = tid & 63;
            float acc = 0.f;
            for (int h = 0; h < HH; h++) {
                float w = w2[h * HH + c];
                float cf = (which == 0) ? w1[h] : (which == 1 ? w1[HH + h] : b1[h]);
                acc += cf * w;
            }
            if (which == 2) acc += b2[c];
            sAB[tid] = acc;
        }
        __syncthreads();
        int raw = tsp[0];
        float ts = (raw > -1000000 && raw < 1000000) ? (float)raw : __int_as_float(raw);
        float p = (ts - arr[row]) / (dep[row] - arr[row]);
        float hd = hard[row];
        float4 xv;
        xv.x = p * sAB[c4]     + hd * sAB[HH + c4]     + sAB[2 * HH + c4];
        xv.y = p * sAB[c4 + 1] + hd * sAB[HH + c4 + 1] + sAB[2 * HH + c4 + 1];
        xv.z = p * sAB[c4 + 2] + hd * sAB[HH + c4 + 2] + sAB[2 * HH + c4 + 2];
        xv.w = p * sAB[c4 + 3] + hd * sAB[HH + c4 + 3] + sAB[2 * HH + c4 + 3];
        *(float4*)&hs[r * HH + c4] = xv;
        *(float4*)&g_x[row * HH + c4] = xv;
        __syncthreads();

        float4 acc = make_float4(0.f, 0.f, 0.f, 0.f);
        #pragma unroll
        for (int k = 0; k < HH; k++) {
            float hv = hs[r * HH + k];
            float4 wv = *(const float4*)&Ws[k * HH + c4];
            acc.x += hv * wv.x; acc.y += hv * wv.y;
            acc.z += hv * wv.z; acc.w += hv * wv.w;
        }
        *(float4*)&g_hw[row * HH + c4] = acc;

        float ps = acc.x * as[c4] + acc.y * as[c4 + 1] + acc.z * as[c4 + 2] + acc.w * as[c4 + 3];
        float pd = acc.x * ad[c4] + acc.y * ad[c4 + 1] + acc.z * ad[c4 + 2] + acc.w * ad[c4 + 3];
        #pragma unroll
        for (int off = 8; off; off >>= 1) {
            ps += __shfl_down_sync(0xffffffffu, ps, off, 16);
            pd += __shfl_down_sync(0xffffffffu, pd, off, 16);
        }
        if ((tid & 15) == 0) { g_src[row] = ps; g_dst[row] = pd; }
    }
    PDL_TRIG();
}

// ---- 2. gemm layers 1,2: 32-row tiles, 128 blocks (single wave) ----
__global__ __launch_bounds__(256) void k_gemm(
        const float* __restrict__ gw, const float* __restrict__ gas,
        const float* __restrict__ gad, int l) {
    __shared__ float Ws[HH * HH];     // 16 KB
    __shared__ float hs[32 * HH];     // 8 KB
    const float* __restrict__ W  = gw + l * HH * HH;
    const float* __restrict__ as = gas + l * HH;
    const float* __restrict__ ad = gad + l * HH;
    int tid = threadIdx.x;            // 256
    int rbase = blockIdx.x * 32;      // 128 blocks
    int r  = tid >> 4;                // 0..15
    int c4 = (tid & 15) * 4;
    int rowA = rbase + r;
    int rowB = rbase + r + 16;

    // weight tile load reads only harness inputs — safe pre-wait preamble
    #pragma unroll
    for (int t = 0; t < 16; t++) Ws[t * 256 + tid] = W[t * 256 + tid];

    PDL_WAIT();                       // g_h from previous attention
    #pragma unroll
    for (int t = 0; t < 8; t++) hs[t * 256 + tid] = g_h[rbase * HH + t * 256 + tid];
    __syncthreads();

    float4 accA = make_float4(0.f, 0.f, 0.f, 0.f);
    float4 accB = make_float4(0.f, 0.f, 0.f, 0.f);
    #pragma unroll
    for (int k = 0; k < HH; k++) {
        float4 wv = *(const float4*)&Ws[k * HH + c4];
        float ha = hs[r * HH + k];
        float hb = hs[(r + 16) * HH + k];
        accA.x += ha * wv.x; accA.y += ha * wv.y;
        accA.z += ha * wv.z; accA.w += ha * wv.w;
        accB.x += hb * wv.x; accB.y += hb * wv.y;
        accB.z += hb * wv.z; accB.w += hb * wv.w;
    }
    *(float4*)&g_hw[rowA * HH + c4] = accA;
    *(float4*)&g_hw[rowB * HH + c4] = accB;

    float psA = accA.x * as[c4] + accA.y * as[c4 + 1] + accA.z * as[c4 + 2] + accA.w * as[c4 + 3];
    float pdA = accA.x * ad[c4] + accA.y * ad[c4 + 1] + accA.z * ad[c4 + 2] + accA.w * ad[c4 + 3];
    float psB = accB.x * as[c4] + accB.y * as[c4 + 1] + accB.z * as[c4 + 2] + accB.w * as[c4 + 3];
    float pdB = accB.x * ad[c4] + accB.y * ad[c4 + 1] + accB.z * ad[c4 + 2] + accB.w * ad[c4 + 3];
    #pragma unroll
    for (int off = 8; off; off >>= 1) {
        psA += __shfl_down_sync(0xffffffffu, psA, off, 16);
        pdA += __shfl_down_sync(0xffffffffu, pdA, off, 16);
        psB += __shfl_down_sync(0xffffffffu, psB, off, 16);
        pdB += __shfl_down_sync(0xffffffffu, pdB, off, 16);
    }
    if ((tid & 15) == 0) {
        g_src[rowA] = psA; g_dst[rowA] = pdA;
        g_src[rowB] = psB; g_dst[rowB] = pdB;
    }
    PDL_TRIG();
}

// shared attention body (2 warps/node); softmax pivoted on self-loop score e0
__device__ __forceinline__ float4 attn_body(int i, int n, int sub, int lane,
                                            const float* __restrict__ b,
                                            float2 (*spj)[MAXD], float2* s_sw,
                                            float4 (*s_accbuf)[16], bool* holds) {
    int deg = g_deg[i];
    if (sub == 0) {
        float di = g_dst[i];
        float e0 = leaky(g_src[i] + di);            // self-loop score = exp pivot
        ushort4 nv = ((const ushort4*)&g_nbr[i * MAXD])[lane];
        int k0 = lane * 4;
        int jj[4] = {nv.x, nv.y, nv.z, nv.w};
        float s = 0.f;
        #pragma unroll
        for (int t = 0; t < 4; t++) {
            if (k0 + t < deg) {
                float e = leaky(g_src[jj[t]] + di);
                float p = __expf(e - e0);           // shift-invariant softmax
                s += p;
                spj[n][k0 + t] = make_float2(p, __int_as_float(jj[t] * HH));
            }
        }
        #pragma unroll
        for (int off = 16; off; off >>= 1) s += __shfl_xor_sync(0xffffffffu, s, off);
        s += 1.0f;                                  // self-loop weight exp(0)=1
        if (lane == 0) s_sw[n] = make_float2(1.0f, 1.0f / s);
    }
    __syncthreads();

    int half = lane >> 4;
    int q    = sub * 2 + half;
    int f4   = (lane & 15) << 2;
    float2 ws = s_sw[n];
    float4 acc = make_float4(0.f, 0.f, 0.f, 0.f);
    if (q == 0) {                                   // self-loop contribution (w=1)
        float4 hv = *(const float4*)&g_hw[i * HH + f4];
        acc.x = hv.x; acc.y = hv.y; acc.z = hv.z; acc.w = hv.w;
    }
    #pragma unroll 4
    for (int k = q; k < deg; k += 4) {
        float2 pj = spj[n][k];
        const float4 hv = *(const float4*)&g_hw[__float_as_int(pj.y) + f4];
        acc.x += pj.x * hv.x; acc.y += pj.x * hv.y;
        acc.z += pj.x * hv.z; acc.w += pj.x * hv.w;
    }
    acc.x += __shfl_xor_sync(0xffffffffu, acc.x, 16);
    acc.y += __shfl_xor_sync(0xffffffffu, acc.y, 16);
    acc.z += __shfl_xor_sync(0xffffffffu, acc.z, 16);
    acc.w += __shfl_xor_sync(0xffffffffu, acc.w, 16);
    if (sub == 1 && half == 0) s_accbuf[n][lane] = acc;
    __syncthreads();
    *holds = (sub == 0 && half == 0);
    float4 o = make_float4(0.f, 0.f, 0.f, 0.f);
    if (*holds) {
        float4 o2 = s_accbuf[n][lane];
        float inv = ws.y;
        o.x = (acc.x + o2.x) * inv + b[f4];
        o.y = (acc.y + o2.y) * inv + b[f4 + 1];
        o.z = (acc.z + o2.z) * inv + b[f4 + 2];
        o.w = (acc.w + o2.w) * inv + b[f4 + 3];
    }
    return o;
}

// builds neighbor list for node i (one warp)
__device__ __forceinline__ void build_nbr(int i, int lane) {
    const unsigned* __restrict__ bm = &g_bits[i * NW];
    unsigned short* __restrict__ nb = &g_nbr[i * MAXD];
    int base = 0;
    #pragma unroll
    for (int r = 0; r < 4; r++) {
        unsigned word = bm[r * 32 + lane];
        int cnt = __popc(word);
        int pre = cnt;
        #pragma unroll
        for (int off = 1; off < 32; off <<= 1) {
            int v = __shfl_up_sync(0xffffffffu, pre, off);
            if (lane >= off) pre += v;
        }
        int total = __shfl_sync(0xffffffffu, pre, 31);
        int o = base + pre - cnt;
        while (word) {
            int b = __ffs(word) - 1; word &= word - 1;
            if (o < MAXD) nb[o] = (unsigned short)(r * 1024 + lane * 32 + b);
            o++;
        }
        base += total;
    }
    if (lane == 0) g_deg[i] = (base < MAXD) ? base : MAXD;
}

// ---- 3. attention layers 0,1: relu + store g_h. l==0 builds nbr lists first. ----
__global__ __launch_bounds__(256) void k_attn(const float* __restrict__ gb, int l) {
    __shared__ float2 spj[4][MAXD];
    __shared__ float2 s_sw[4];
    __shared__ float4 s_accbuf[4][16];
    PDL_WAIT();                           // fused kernel (bits+gemm0) or gemm_l
    int warp = threadIdx.x >> 5, lane = threadIdx.x & 31;
    int n = warp >> 1, sub = warp & 1;
    int i = blockIdx.x * 4 + n;           // 1024 blocks
    if (l == 0) {
        if (sub == 0) build_nbr(i, lane);
        __syncthreads();                  // g_deg/g_nbr visible block-wide
    }
    bool holds;
    float4 o = attn_body(i, n, sub, lane, gb + l * HH, spj, s_sw, s_accbuf, &holds);
    if (holds) {
        o.x = fmaxf(o.x, 0.f); o.y = fmaxf(o.y, 0.f);
        o.z = fmaxf(o.z, 0.f); o.w = fmaxf(o.w, 0.f);
        *(float4*)&g_h[i * HH + ((lane & 15) << 2)] = o;
    }
    PDL_TRIG();
}

// ---- 4. attention layer 2 fused with residual+layernorm+value+global reduce ----
__global__ __launch_bounds__(256) void k_attn2(const float* __restrict__ gb,
                                               const float* __restrict__ vw,
                                               const float* __restrict__ vb,
                                               float* __restrict__ out) {
    __shared__ float2 spj[4][MAXD];
    __shared__ float2 s_sw[4];
    __shared__ float4 s_accbuf[4][16];
    __shared__ float s_node[4];
    __shared__ int islast;
    __shared__ float s_red[256];
    PDL_WAIT();
    int warp = threadIdx.x >> 5, lane = threadIdx.x & 31;
    int n = warp >> 1, sub = warp & 1;
    int i = blockIdx.x * 4 + n;           // 1024 blocks
    bool holds;
    float4 o = attn_body(i, n, sub, lane, gb + 2 * HH, spj, s_sw, s_accbuf, &holds);

    if (holds) {                          // 16 lanes of warp sub==0 per node
        int f4 = (lane & 15) << 2;
        float4 xv = *(const float4*)&g_x[i * HH + f4];
        float v0 = xv.x + o.x, v1 = xv.y + o.y, v2 = xv.z + o.z, v3 = xv.w + o.w;
        float sm = v0 + v1 + v2 + v3;
        #pragma unroll
        for (int off = 8; off; off >>= 1) sm += __shfl_xor_sync(0x0000ffffu, sm, off, 16);
        float mu = sm * (1.0f / 64.0f);
        float d0 = v0 - mu, d1 = v1 - mu, d2 = v2 - mu, d3 = v3 - mu;
        float vs = d0 * d0 + d1 * d1 + d2 * d2 + d3 * d3;
        #pragma unroll
        for (int off = 8; off; off >>= 1) vs += __shfl_xor_sync(0x0000ffffu, vs, off, 16);
        float rstd = rsqrtf(vs * (1.0f / 64.0f) + EPSV);
        float yr = (d0 * vw[f4] + d1 * vw[f4 + 1] + d2 * vw[f4 + 2] + d3 * vw[f4 + 3]) * rstd;
        #pragma unroll
        for (int off = 8; off; off >>= 1) yr += __shfl_xor_sync(0x0000ffffu, yr, off, 16);
        if (lane == 0) s_node[n] = yr;
    }
    __syncthreads();
    if (threadIdx.x == 0) {
        float t = s_node[0] + s_node[1] + s_node[2] + s_node[3];   // fixed order
        g_part[blockIdx.x] = t;
        __threadfence();
        islast = (atomicAdd(&g_cnt, 1) == 1023);
    }
    __syncthreads();
    if (islast) {
        __threadfence();
        int tid = threadIdx.x;
        float v = 0.f;
        #pragma unroll
        for (int k = 0; k < 4; k++) v += g_part[tid + k * 256];    // fixed order
        s_red[tid] = v;
        __syncthreads();
        #pragma unroll
        for (int off = 128; off; off >>= 1) {
            if (tid < off) s_red[tid] += s_red[tid + off];
            __syncthreads();
        }
        if (tid == 0)
            out[0] = fmaxf(0.0f, s_red[0] * (1.0f / NN) + vb[0]);
    }
}

static void launch_pdl(void* func, dim3 grid, dim3 block, void** args) {
    cudaLaunchConfig_t cfg = {};
    cfg.gridDim = grid;
    cfg.blockDim = block;
    cfg.stream = 0;
    cudaLaunchAttribute attr[1];
    attr[0].id = cudaLaunchAttributeProgrammaticStreamSerialization;
    attr[0].val.programmaticStreamSerializationAllowed = 1;
    cfg.attrs = attr;
    cfg.numAttrs = 1;
    cudaLaunchKernelExC(&cfg, func, args);
}

extern "C" void kernel_launch(void* const* d_in, const int* in_sizes, int n_in,
                              void* d_out, int out_size) {
    const float* adj  = (const float*)d_in[0];
    const int*   ts   = (const int*)  d_in[1];
    const float* arr  = (const float*)d_in[2];
    const float* dep  = (const float*)d_in[3];
    const float* hard = (const float*)d_in[4];
    const float* w1 = (const float*)d_in[6];
    const float* b1 = (const float*)d_in[7];
    const float* w2 = (const float*)d_in[8];
    const float* b2 = (const float*)d_in[9];
    const float* gw  = (const float*)d_in[10];
    const float* gas = (const float*)d_in[11];
    const float* gad = (const float*)d_in[12];
    const float* gb  = (const float*)d_in[13];
    const float* vw  = (const float*)d_in[14];
    const float* vb  = (const float*)d_in[15];
    float* out = (float*)d_out;

    k_fuse0<<<768, 256>>>(adj, gw, gas, gad, w1, b1, w2, b2, ts, arr, dep, hard);

    {   int l0 = 0;
        void* aa[] = {(void*)&gb, (void*)&l0};
        launch_pdl((void*)k_attn, dim3(1024), dim3(256), aa); }

    for (int l = 1; l < LL; l++) {
        void* ga[] = {(void*)&gw, (void*)&gas, (void*)&gad, (void*)&l};
        launch_pdl((void*)k_gemm, dim3(128), dim3(256), ga);
        if (l < LL - 1) {
            void* aa[] = {(void*)&gb, (void*)&l};
            launch_pdl((void*)k_attn, dim3(1024), dim3(256), aa);
        } else {
            void* aa[] = {(void*)&gb, (void*)&vw, (void*)&vb, (void*)&out};
            launch_pdl((void*)k_attn2, dim3(1024), dim3(256), aa);
        }
    }
}